// round 6
// baseline (speedup 1.0000x reference)
#include <cuda_runtime.h>
#include <math.h>

// ---------------- problem constants ----------------
#define HDIM   256
#define NL     6
#define NSTATE 64
#define DIN    512
#define HEADS  8
#define PDIM   64
#define CONVD  640          // DIN + 2*N
#define PROJ   1160         // 2*DIN + 2*N + HEADS
#define TOK    65536        // tokens per mamba call (128*512 == 1024*64)
#define XELEMS (2ull*512ull*64ull*HDIM)   // 16,777,216

// ---------------- scratch (device globals; no allocation allowed) ----------------
__device__ float g_bufA[XELEMS];
__device__ float g_bufB[XELEMS];
__device__ float g_xn [(size_t)TOK * HDIM];
__device__ float g_zx [(size_t)TOK * PROJ];
__device__ float g_xbc[(size_t)TOK * CONVD];
__device__ float g_dt [(size_t)TOK * HEADS];
__device__ float g_dA [(size_t)TOK * HEADS];
__device__ float g_y  [(size_t)TOK * DIN];     // scan output; gate writes in-place

// ---------------- rmsnorm over 256 (outer norm) : one warp / token ----------------
__global__ __launch_bounds__(256) void rms256_k(const float* __restrict__ x,
                                                const float* __restrict__ w,
                                                float* __restrict__ out)
{
    int warp = (blockIdx.x * blockDim.x + threadIdx.x) >> 5;   // token id
    int lane = threadIdx.x & 31;
    const float* row = x + (size_t)warp * HDIM;
    float v[8]; float ss = 0.f;
#pragma unroll
    for (int i = 0; i < 8; i++) { v[i] = row[lane + i*32]; ss += v[i]*v[i]; }
#pragma unroll
    for (int o = 16; o > 0; o >>= 1) ss += __shfl_xor_sync(0xffffffffu, ss, o);
    float rs = rsqrtf(ss * (1.f/256.f) + 1e-6f);
    float* orow = out + (size_t)warp * HDIM;
#pragma unroll
    for (int i = 0; i < 8; i++) { int c = lane + i*32; orow[c] = v[i] * rs * w[c]; }
}

// ---------------- dt = softplus(raw+dtb), dA = exp(-exp(Alog)*dt) ----------------
__global__ __launch_bounds__(256) void dtda_k(const float* __restrict__ zx,
                                              const float* __restrict__ dtb,
                                              const float* __restrict__ Alog,
                                              float* __restrict__ dt,
                                              float* __restrict__ dA)
{
    int i = blockIdx.x * blockDim.x + threadIdx.x;   // TOK*HEADS threads exactly
    int t  = i >> 3;
    int hh = i & 7;
    float v = zx[(size_t)t * PROJ + (DIN + CONVD) + hh] + dtb[hh];
    float sp = (v > 20.f) ? v : log1pf(expf(v));
    dt[i] = sp;
    dA[i] = expf(-expf(Alog[hh]) * sp);
}

// ---------------- causal depthwise conv (k=4) + SiLU over 640 channels ----------------
__global__ __launch_bounds__(128) void conv_k(const float* __restrict__ zx,
                                              const float* __restrict__ cw,  // [4,640]
                                              const float* __restrict__ cb,  // [640]
                                              float* __restrict__ xbc,       // [T,640]
                                              int L)
{
    int s = blockIdx.x;
    int c = blockIdx.y * 128 + threadIdx.x;       // 0..639
    float w0 = cw[c], w1 = cw[640 + c], w2 = cw[1280 + c], w3 = cw[1920 + c];
    float bias = cb[c];
    const float* in  = zx  + (size_t)s * L * PROJ + DIN + c;
    float*       out = xbc + (size_t)s * L * CONVD + c;
    float x0 = 0.f, x1 = 0.f, x2 = 0.f;
    for (int l = 0; l < L; ++l) {
        float x3 = in[(size_t)l * PROJ];
        float v  = bias + w0*x0 + w1*x1 + w2*x2 + w3*x3;
        out[(size_t)l * CONVD] = v / (1.f + __expf(-v));   // silu
        x0 = x1; x1 = x2; x2 = x3;
    }
}

// ---------------- SSM scan: one CTA per sequence, thread = (head,p), h[64] in regs ----
__global__ __launch_bounds__(512, 1) void scan_k(const float* __restrict__ xbc,
                                                 const float* __restrict__ dt,
                                                 const float* __restrict__ dA,
                                                 const float* __restrict__ Dp,
                                                 float* __restrict__ y,
                                                 int L)
{
    int s   = blockIdx.x;
    int tid = threadIdx.x;           // 512: head = tid>>6, p = tid&63
    int hh  = tid >> 6;
    __shared__ float sB[2][64], sC[2][64], sdt[2][8], sdA[2][8];
    float h[64];
#pragma unroll
    for (int n = 0; n < 64; n++) h[n] = 0.f;
    float Dh = Dp[hh];
    size_t base = (size_t)s * L;

    for (int l = 0; l < L; ++l) {
        int buf = l & 1;
        const float* row = xbc + (base + l) * CONVD;
        if (tid < 128) {
            float val = row[DIN + tid];
            if (tid < 64) sB[buf][tid] = val; else sC[buf][tid - 64] = val;
        } else if (tid < 136) {
            sdt[buf][tid - 128] = dt[(base + l) * HEADS + (tid - 128)];
        } else if (tid < 144) {
            sdA[buf][tid - 136] = dA[(base + l) * HEADS + (tid - 136)];
        }
        float xv = row[tid];                       // xs value for (head,p)
        __syncthreads();                           // one barrier per step
        float a   = sdA[buf][hh];
        float xdt = xv * sdt[buf][hh];
        float acc0 = 0.f, acc1 = 0.f, acc2 = 0.f, acc3 = 0.f;
#pragma unroll
        for (int n4 = 0; n4 < 16; ++n4) {
            float4 b4 = *(const float4*)&sB[buf][n4 * 4];
            float4 c4 = *(const float4*)&sC[buf][n4 * 4];
            int n = n4 * 4;
            h[n+0] = fmaf(a, h[n+0], xdt * b4.x); acc0 = fmaf(h[n+0], c4.x, acc0);
            h[n+1] = fmaf(a, h[n+1], xdt * b4.y); acc1 = fmaf(h[n+1], c4.y, acc1);
            h[n+2] = fmaf(a, h[n+2], xdt * b4.z); acc2 = fmaf(h[n+2], c4.z, acc2);
            h[n+3] = fmaf(a, h[n+3], xdt * b4.w); acc3 = fmaf(h[n+3], c4.w, acc3);
        }
        y[(base + l) * DIN + tid] = ((acc0 + acc1) + (acc2 + acc3)) + Dh * xv;
    }
}

// ---------- gate (y * silu(z)) + rmsnorm-512 with gn, IN PLACE over y ------------
__global__ __launch_bounds__(256) void gate_k(float* __restrict__ y,
                                              const float* __restrict__ zx,
                                              const float* __restrict__ gn)
{
    int warp = (blockIdx.x * blockDim.x + threadIdx.x) >> 5;   // token id
    int lane = threadIdx.x & 31;
    float* yrow = y + (size_t)warp * DIN;
    const float* zrow = zx + (size_t)warp * PROJ;              // z = cols [0,512)
    float v[16]; float ss = 0.f;
#pragma unroll
    for (int i = 0; i < 16; i++) {
        int c = lane + i*32;
        float z  = zrow[c];
        float gv = yrow[c] * (z / (1.f + __expf(-z)));
        v[i] = gv; ss += gv * gv;
    }
#pragma unroll
    for (int o = 16; o > 0; o >>= 1) ss += __shfl_xor_sync(0xffffffffu, ss, o);
    float rs = rsqrtf(ss * (1.f/512.f) + 1e-6f);
#pragma unroll
    for (int i = 0; i < 16; i++) { int c = lane + i*32; yrow[c] = v[i] * rs * gn[c]; }
}

// ---------------- SGEMM: C[M,N] = (Res?) + A[M,K] @ B[K,N], row-major, fp32 ----------
#define BM 128
#define BN 128
#define BK 8
__global__ __launch_bounds__(256, 2) void sgemm_k(int M, int N, int K,
                                                  const float* __restrict__ A,
                                                  const float* __restrict__ B,
                                                  const float* __restrict__ Res,
                                                  float* __restrict__ C)
{
    __shared__ float As[BK][BM];      // A tile, transposed
    __shared__ float Bs[BK][BN];
    int tid  = threadIdx.x;
    size_t row0 = (size_t)blockIdx.y * BM;
    int    col0 = blockIdx.x * BN;

    int a_r = tid >> 1;               // 0..127
    int a_k = (tid & 1) << 2;         // 0 or 4
    int b_k = tid >> 5;               // 0..7
    int b_c = (tid & 31) << 2;        // 0..124
    int tx  = tid & 15, ty = tid >> 4;

    const float* Aptr = A + (row0 + a_r) * K + a_k;
    const float* Bptr = B + (size_t)b_k * N + col0 + b_c;
    bool bval = (col0 + b_c) < N;     // N % 4 == 0 for all our shapes

    float acc[8][8];
#pragma unroll
    for (int i = 0; i < 8; i++)
#pragma unroll
        for (int j = 0; j < 8; j++) acc[i][j] = 0.f;

    int KT = K / BK;
    float4 av = *(const float4*)Aptr;
    float4 bv = bval ? *(const float4*)Bptr : make_float4(0.f, 0.f, 0.f, 0.f);

    for (int kt = 0; kt < KT; ++kt) {
        As[a_k+0][a_r] = av.x; As[a_k+1][a_r] = av.y;
        As[a_k+2][a_r] = av.z; As[a_k+3][a_r] = av.w;
        *(float4*)&Bs[b_k][b_c] = bv;
        __syncthreads();
        if (kt + 1 < KT) {            // register prefetch overlaps compute
            av = *(const float4*)(Aptr + (kt + 1) * BK);
            bv = bval ? *(const float4*)(Bptr + (size_t)(kt + 1) * BK * N)
                      : make_float4(0.f, 0.f, 0.f, 0.f);
        }
#pragma unroll
        for (int k = 0; k < BK; ++k) {
            float4 a0 = *(const float4*)&As[k][ty*8];
            float4 a1 = *(const float4*)&As[k][ty*8 + 4];
            float4 b0 = *(const float4*)&Bs[k][tx*8];
            float4 b1 = *(const float4*)&Bs[k][tx*8 + 4];
            float af[8] = {a0.x,a0.y,a0.z,a0.w,a1.x,a1.y,a1.z,a1.w};
            float bf[8] = {b0.x,b0.y,b0.z,b0.w,b1.x,b1.y,b1.z,b1.w};
#pragma unroll
            for (int i = 0; i < 8; i++)
#pragma unroll
                for (int j = 0; j < 8; j++)
                    acc[i][j] = fmaf(af[i], bf[j], acc[i][j]);
        }
        __syncthreads();
    }
#pragma unroll
    for (int i = 0; i < 8; i++) {
        size_t r = row0 + ty*8 + i;
#pragma unroll
        for (int j = 0; j < 8; j += 4) {
            int c = col0 + tx*8 + j;
            if (c < N) {
                float4 o; o.x = acc[i][j]; o.y = acc[i][j+1];
                          o.z = acc[i][j+2]; o.w = acc[i][j+3];
                if (Res) {
                    float4 rv = *(const float4*)&Res[r * N + c];
                    o.x += rv.x; o.y += rv.y; o.z += rv.z; o.w += rv.w;
                }
                *(float4*)&C[r * N + c] = o;
            }
        }
    }
}

// ---------------- transpose (2,64,512,H) -> (2,512,64,H), float4 granularity --------
__global__ __launch_bounds__(256) void transpose_k(const float* __restrict__ in,
                                                   float* __restrict__ out)
{
    size_t id = (size_t)blockIdx.x * 256 + threadIdx.x;   // over 2*512*64*64 float4s
    int h4   = (int)(id & 63);
    int band = (int)((id >> 6) & 63);
    int t    = (int)((id >> 12) & 511);
    int b    = (int)(id >> 21);
    const float4* ip = (const float4*)in;
    ((float4*)out)[id] = ip[((((size_t)(b * 64 + band)) * 512 + t) << 6) + h4];
}

// ---------------- host-side orchestration ----------------
static void run_mamba(const float* io_in, float* io_out, int S, int L,
                      const float* norm, const float* Win, const float* cw,
                      const float* cb, const float* dtb, const float* Alog,
                      const float* Dp, const float* gn, const float* Wout,
                      float* xn, float* zx, float* xbc, float* dtp, float* dAp,
                      float* yb)
{
    rms256_k<<<TOK / 8, 256>>>(io_in, norm, xn);
    {
        dim3 grid((PROJ + BN - 1) / BN, TOK / BM);
        sgemm_k<<<grid, 256>>>(TOK, PROJ, HDIM, xn, Win, nullptr, zx);
    }
    dtda_k<<<(TOK * HEADS) / 256, 256>>>(zx, dtb, Alog, dtp, dAp);
    {
        dim3 grid(S, CONVD / 128);
        conv_k<<<grid, 128>>>(zx, cw, cb, xbc, L);
    }
    scan_k<<<S, 512>>>(xbc, dtp, dAp, Dp, yb, L);
    gate_k<<<TOK / 8, 256>>>(yb, zx, gn);
    {
        dim3 grid(HDIM / BN, TOK / BM);
        sgemm_k<<<grid, 256>>>(TOK, HDIM, DIN, yb, Wout, io_in, io_out);
    }
}

extern "C" void kernel_launch(void* const* d_in, const int* in_sizes, int n_in,
                              void* d_out, int out_size)
{
    const float* x      = (const float*)d_in[0];
    const float* t_norm = (const float*)d_in[1];
    const float* t_Win  = (const float*)d_in[2];
    const float* t_cw   = (const float*)d_in[3];
    const float* t_cb   = (const float*)d_in[4];
    const float* t_dtb  = (const float*)d_in[5];
    const float* t_Alog = (const float*)d_in[6];
    const float* t_D    = (const float*)d_in[7];
    const float* t_gn   = (const float*)d_in[8];
    const float* t_Wout = (const float*)d_in[9];
    const float* b_norm = (const float*)d_in[10];
    const float* b_Win  = (const float*)d_in[11];
    const float* b_cw   = (const float*)d_in[12];
    const float* b_cb   = (const float*)d_in[13];
    const float* b_dtb  = (const float*)d_in[14];
    const float* b_Alog = (const float*)d_in[15];
    const float* b_D    = (const float*)d_in[16];
    const float* b_gn   = (const float*)d_in[17];
    const float* b_Wout = (const float*)d_in[18];

    float *bufA, *bufB, *xn, *zx, *xbc, *dtp, *dAp, *yb;
    cudaGetSymbolAddress((void**)&bufA, g_bufA);
    cudaGetSymbolAddress((void**)&bufB, g_bufB);
    cudaGetSymbolAddress((void**)&xn,  g_xn);
    cudaGetSymbolAddress((void**)&zx,  g_zx);
    cudaGetSymbolAddress((void**)&xbc, g_xbc);
    cudaGetSymbolAddress((void**)&dtp, g_dt);
    cudaGetSymbolAddress((void**)&dAp, g_dA);
    cudaGetSymbolAddress((void**)&yb,  g_y);

    cudaMemcpyAsync(bufA, x, XELEMS * sizeof(float), cudaMemcpyDeviceToDevice);

    float* cur = bufA;
    float* alt = bufB;
    const size_t nF4 = XELEMS / 4;                // 4,194,304 float4s

    for (int i = 0; i < NL; ++i) {
        // time path: flat buffer viewed as 128 contiguous sequences of 512 tokens
        run_mamba(cur, cur, 128, 512,
                  t_norm + (size_t)i * HDIM,
                  t_Win  + (size_t)i * HDIM * PROJ,
                  t_cw   + (size_t)i * 4 * CONVD,
                  t_cb   + (size_t)i * CONVD,
                  t_dtb  + (size_t)i * HEADS,
                  t_Alog + (size_t)i * HEADS,
                  t_D    + (size_t)i * HEADS,
                  t_gn   + (size_t)i * DIN,
                  t_Wout + (size_t)i * DIN * HDIM,
                  xn, zx, xbc, dtp, dAp, yb);

        // (2,64,512,H) -> (2,512,64,H)
        transpose_k<<<(unsigned)(nF4 / 256), 256>>>(cur, alt);
        { float* tmp = cur; cur = alt; alt = tmp; }

        // band path: flat buffer viewed as 1024 contiguous sequences of 64 tokens
        run_mamba(cur, cur, 1024, 64,
                  b_norm + (size_t)i * HDIM,
                  b_Win  + (size_t)i * HDIM * PROJ,
                  b_cw   + (size_t)i * 4 * CONVD,
                  b_cb   + (size_t)i * CONVD,
                  b_dtb  + (size_t)i * HEADS,
                  b_Alog + (size_t)i * HEADS,
                  b_D    + (size_t)i * HEADS,
                  b_gn   + (size_t)i * DIN,
                  b_Wout + (size_t)i * DIN * HDIM,
                  xn, zx, xbc, dtp, dAp, yb);
        // next layer's time path reinterprets this contiguous buffer directly
    }

    cudaMemcpyAsync(d_out, cur, XELEMS * sizeof(float), cudaMemcpyDeviceToDevice);
}

// round 9
// speedup vs baseline: 1.7031x; 1.7031x over previous
#include <cuda_runtime.h>
#include <cuda_bf16.h>
#include <math.h>
#include <stdint.h>

// ---------------- problem constants ----------------
#define HDIM   256
#define NL     6
#define NSTATE 64
#define DIN    512
#define HEADS  8
#define PDIM   64
#define CONVD  640          // DIN + 2*N
#define PROJ   1160         // 2*DIN + 2*N + HEADS
#define NPAD   1280         // PROJ padded to multiple of 128
#define TOK    65536        // tokens per mamba call (128*512 == 1024*64)
#define XELEMS (2ull*512ull*64ull*HDIM)   // 16,777,216

// ---------------- scratch (device globals; no allocation allowed) ----------------
__device__ float g_bufA[XELEMS];
__device__ float g_bufB[XELEMS];
__device__ float g_zx [(size_t)TOK * PROJ];
__device__ float g_xbc[(size_t)TOK * CONVD];
__device__ float g_dt [(size_t)TOK * HEADS];
__device__ float g_dA [(size_t)TOK * HEADS];
__device__ float g_y  [(size_t)TOK * DIN];     // scan output
__device__ __nv_bfloat16 g_xh[(size_t)TOK * DIN];   // GEMM A operand, hi part
__device__ __nv_bfloat16 g_xl[(size_t)TOK * DIN];   // GEMM A operand, lo part
__device__ __nv_bfloat16 g_WinTh [12][(size_t)NPAD * HDIM];
__device__ __nv_bfloat16 g_WinTl [12][(size_t)NPAD * HDIM];
__device__ __nv_bfloat16 g_WoutTh[12][(size_t)HDIM * DIN];
__device__ __nv_bfloat16 g_WoutTl[12][(size_t)HDIM * DIN];

// ================= PTX helpers (baseline ISA only, no 'a'-features) =================
__device__ __forceinline__ uint32_t smem_u32(const void* p) {
    uint32_t a;
    asm("{ .reg .u64 t; cvta.to.shared.u64 t, %1; cvt.u32.u64 %0, t; }" : "=r"(a) : "l"(p));
    return a;
}
#define CP_ASYNC16(dst, src) \
    asm volatile("cp.async.cg.shared.global [%0], [%1], 16;" :: "r"(dst), "l"(src))
#define CP_COMMIT() asm volatile("cp.async.commit_group;" ::: "memory")
#define CP_WAIT0()  asm volatile("cp.async.wait_group 0;" ::: "memory")
#define CP_WAIT1()  asm volatile("cp.async.wait_group 1;" ::: "memory")
#define LDSM_X4(r0, r1, r2, r3, addr) \
    asm volatile("ldmatrix.sync.aligned.m8n8.x4.shared.b16 {%0,%1,%2,%3}, [%4];" \
        : "=r"(r0), "=r"(r1), "=r"(r2), "=r"(r3) : "r"(addr))
#define MMA_BF16(d, a, b) \
    asm volatile("mma.sync.aligned.m16n8k16.row.col.f32.bf16.bf16.f32 " \
        "{%0,%1,%2,%3}, {%4,%5,%6,%7}, {%8,%9}, {%0,%1,%2,%3};" \
        : "+f"((d)[0]), "+f"((d)[1]), "+f"((d)[2]), "+f"((d)[3]) \
        : "r"((a)[0]), "r"((a)[1]), "r"((a)[2]), "r"((a)[3]), \
          "r"((b)[0]), "r"((b)[1]))

__device__ __forceinline__ uint32_t swz(uint32_t off) { return off ^ ((off >> 3) & 0x70); }

// ================= bf16x3 HMMA GEMM =================
// C[M,Nlog] = (Res?) + (Ah+Al)[M,K] @ (Bh+Bl)[Npad,K]^T, dropping Al*Bl.
// tile 128x128, K-chunk 64 (= 128B SW128 row), cp.async 2-stage, 256 threads.
// smem per stage (64KB): Ah | Al | Bh | Bl, 16KB each (128 rows x 128B swizzled).
#define GEMM_SMEM (2 * 65536)
__global__ __launch_bounds__(256, 1) void mma_gemm_k(int N, int K,
        const __nv_bfloat16* __restrict__ Ah, const __nv_bfloat16* __restrict__ Al,
        const __nv_bfloat16* __restrict__ Bh, const __nv_bfloat16* __restrict__ Bl,
        const float* __restrict__ Res, float* __restrict__ C)
{
    extern __shared__ __align__(1024) char smem[];
    uint32_t sb = smem_u32(smem);
    int tid  = threadIdx.x;
    int wid  = tid >> 5, lane = tid & 31;
    size_t row0 = (size_t)blockIdx.y * 128;
    size_t nr0  = (size_t)blockIdx.x * 128;
    int    n0   = blockIdx.x * 128;

    const __nv_bfloat16* mats[4] = { Ah, Al, Bh, Bl };

    const int NC = K >> 6;      // K-chunks of 64 bf16 (=128B rows)

    auto load_stage = [&](int c) {
        uint32_t st = sb + (uint32_t)(c & 1) * 65536;
        int kofs = c << 6;
#pragma unroll
        for (int m = 0; m < 4; ++m) {
            size_t rbase = (m < 2) ? row0 : nr0;
            const char* P = (const char*)(mats[m] + rbase * K + kofs);
            uint32_t dst = st + m * 16384;
#pragma unroll
            for (int i = 0; i < 4; ++i) {
                int seg = i * 256 + tid;          // 1024 16B segments per matrix
                int row = seg >> 3, sj = seg & 7;
                CP_ASYNC16(dst + swz(row * 128 + sj * 16),
                           P + (size_t)row * K * 2 + sj * 16);
            }
        }
        CP_COMMIT();
    };

    float acc[4][4][4];
#pragma unroll
    for (int i = 0; i < 4; ++i)
#pragma unroll
        for (int j = 0; j < 4; ++j)
#pragma unroll
            for (int q = 0; q < 4; ++q) acc[i][j][q] = 0.f;

    int wm = wid >> 2, wn = wid & 3;      // warps 2(m) x 4(n)
    int m0w = wm * 64, n0w = wn * 32;
    int lm = lane & 7;                     // row within 8x8 matrix
    int li = lane >> 3;                    // which of the 4 matrices

    load_stage(0);
    for (int c = 0; c < NC; ++c) {
        bool pf = (c + 1 < NC);
        if (pf) load_stage(c + 1);
        if (pf) CP_WAIT1(); else CP_WAIT0();
        __syncthreads();

        uint32_t st  = sb + (uint32_t)(c & 1) * 65536;
        uint32_t aph = st, apl = st + 16384, bph = st + 32768, bpl = st + 49152;
#pragma unroll
        for (int k16 = 0; k16 < 4; ++k16) {
            uint32_t Ahf[4][4], Alf[4][4], Bhf[4][2], Blf[4][2];
            // A: matrix j -> rows +((j&1)*8), col16 +(j>>1)
            {
                int rA   = m0w + ((li & 1) << 3) + lm;
                int c16A = k16 * 2 + (li >> 1);
#pragma unroll
                for (int ma = 0; ma < 4; ++ma) {
                    uint32_t off = swz((uint32_t)(rA + ma * 16) * 128 + c16A * 16);
                    LDSM_X4(Ahf[ma][0], Ahf[ma][1], Ahf[ma][2], Ahf[ma][3], aph + off);
                    LDSM_X4(Alf[ma][0], Alf[ma][1], Alf[ma][2], Alf[ma][3], apl + off);
                }
            }
            // B (stored [n][k] -> col-major B): matrix j -> n-rows +((j>>1)*8), col16 +(j&1)
            {
                int rB   = n0w + ((li >> 1) << 3) + lm;
                int c16B = k16 * 2 + (li & 1);
#pragma unroll
                for (int nb = 0; nb < 2; ++nb) {
                    uint32_t off = swz((uint32_t)(rB + nb * 16) * 128 + c16B * 16);
                    LDSM_X4(Bhf[nb*2][0], Bhf[nb*2][1], Bhf[nb*2+1][0], Bhf[nb*2+1][1], bph + off);
                    LDSM_X4(Blf[nb*2][0], Blf[nb*2][1], Blf[nb*2+1][0], Blf[nb*2+1][1], bpl + off);
                }
            }
#pragma unroll
            for (int ma = 0; ma < 4; ++ma)
#pragma unroll
                for (int na = 0; na < 4; ++na) {
                    MMA_BF16(acc[ma][na], Ahf[ma], Bhf[na]);
                    MMA_BF16(acc[ma][na], Ahf[ma], Blf[na]);
                    MMA_BF16(acc[ma][na], Alf[ma], Bhf[na]);
                }
        }
        __syncthreads();
    }

    // epilogue: c0,c1 -> row g, cols t*2,t*2+1 ; c2,c3 -> row g+8
    int gid = lane >> 2, tig = lane & 3;
#pragma unroll
    for (int ma = 0; ma < 4; ++ma) {
        size_t r0g = row0 + m0w + ma * 16 + gid;
#pragma unroll
        for (int na = 0; na < 4; ++na) {
            int cc = n0 + n0w + na * 8 + tig * 2;
            if (cc < N) {
                float2 v0 = make_float2(acc[ma][na][0], acc[ma][na][1]);
                float2 v1 = make_float2(acc[ma][na][2], acc[ma][na][3]);
                if (Res) {
                    float2 r0v = *(const float2*)&Res[r0g * N + cc];
                    float2 r1v = *(const float2*)&Res[(r0g + 8) * N + cc];
                    v0.x += r0v.x; v0.y += r0v.y; v1.x += r1v.x; v1.y += r1v.y;
                }
                *(float2*)&C[r0g * N + cc]       = v0;
                *(float2*)&C[(r0g + 8) * N + cc] = v1;
            }
        }
    }
}

// ------- weight transpose+split: W[K,N] -> WTh/WTl[Npad,K] (bf16 hi/lo) -------
__global__ __launch_bounds__(256) void wtrans_k(const float* __restrict__ W,
                                                __nv_bfloat16* __restrict__ WTh,
                                                __nv_bfloat16* __restrict__ WTl,
                                                int K, int N, int Npad)
{
    int idx = blockIdx.x * 256 + threadIdx.x;
    if (idx >= Npad * K) return;
    int n = idx / K, k = idx - n * K;
    float v = (n < N) ? W[(size_t)k * N + n] : 0.f;
    __nv_bfloat16 h = __float2bfloat16(v);
    WTh[idx] = h;
    WTl[idx] = __float2bfloat16(v - __bfloat162float(h));
}

// ---------------- rmsnorm-256 -> bf16 hi/lo : one warp / token ----------------
__global__ __launch_bounds__(256) void rms256_k(const float* __restrict__ x,
                                                const float* __restrict__ w,
                                                __nv_bfloat16* __restrict__ oh,
                                                __nv_bfloat16* __restrict__ ol)
{
    int warp = (blockIdx.x * blockDim.x + threadIdx.x) >> 5;
    int lane = threadIdx.x & 31;
    const float* row = x + (size_t)warp * HDIM;
    float v[8]; float ss = 0.f;
#pragma unroll
    for (int i = 0; i < 8; i++) { v[i] = row[lane + i*32]; ss += v[i]*v[i]; }
#pragma unroll
    for (int o = 16; o > 0; o >>= 1) ss += __shfl_xor_sync(0xffffffffu, ss, o);
    float rs = rsqrtf(ss * (1.f/256.f) + 1e-6f);
    __nv_bfloat16* hrow = oh + (size_t)warp * HDIM;
    __nv_bfloat16* lrow = ol + (size_t)warp * HDIM;
#pragma unroll
    for (int i = 0; i < 8; i++) {
        int c = lane + i*32;
        float f = v[i] * rs * w[c];
        __nv_bfloat16 h = __float2bfloat16(f);
        hrow[c] = h;
        lrow[c] = __float2bfloat16(f - __bfloat162float(h));
    }
}

// ---------------- dt = softplus(raw+dtb), dA = exp(-exp(Alog)*dt) ----------------
__global__ __launch_bounds__(256) void dtda_k(const float* __restrict__ zx,
                                              const float* __restrict__ dtb,
                                              const float* __restrict__ Alog,
                                              float* __restrict__ dt,
                                              float* __restrict__ dA)
{
    int i = blockIdx.x * blockDim.x + threadIdx.x;
    int t  = i >> 3;
    int hh = i & 7;
    float v = zx[(size_t)t * PROJ + (DIN + CONVD) + hh] + dtb[hh];
    float sp = (v > 20.f) ? v : log1pf(expf(v));
    dt[i] = sp;
    dA[i] = expf(-expf(Alog[hh]) * sp);
}

// ------- causal depthwise conv (k=4) + SiLU, parallel over 64-step L-chunks -------
__global__ __launch_bounds__(128) void conv_k(const float* __restrict__ zx,
                                              const float* __restrict__ cw,
                                              const float* __restrict__ cb,
                                              float* __restrict__ xbc,
                                              int L, int nch)
{
    int bx = blockIdx.x;
    int s  = bx / nch;
    int ch = bx - s * nch;
    int c  = blockIdx.y * 128 + threadIdx.x;
    int l0 = ch * 64;
    float w0 = cw[c], w1 = cw[640 + c], w2 = cw[1280 + c], w3 = cw[1920 + c];
    float bias = cb[c];
    const float* in  = zx  + ((size_t)s * L + l0) * PROJ + DIN + c;
    float*       out = xbc + ((size_t)s * L + l0) * CONVD + c;
    float x0 = (l0 > 0) ? in[-3 * PROJ] : 0.f;
    float x1 = (l0 > 0) ? in[-2 * PROJ] : 0.f;
    float x2 = (l0 > 0) ? in[-1 * PROJ] : 0.f;
    for (int l = 0; l < 64; ++l) {
        float x3 = in[(size_t)l * PROJ];
        float v  = bias + w0*x0 + w1*x1 + w2*x2 + w3*x3;
        out[(size_t)l * CONVD] = v / (1.f + __expf(-v));
        x0 = x1; x1 = x2; x2 = x3;
    }
}

// ---------------- SSM scan: one CTA per sequence ----------------
__global__ __launch_bounds__(512, 1) void scan_k(const float* __restrict__ xbc,
                                                 const float* __restrict__ dt,
                                                 const float* __restrict__ dA,
                                                 const float* __restrict__ Dp,
                                                 float* __restrict__ y,
                                                 int L)
{
    int s   = blockIdx.x;
    int tid = threadIdx.x;
    int hh  = tid >> 6;
    __shared__ float sB[2][64], sC[2][64], sdt[2][8], sdA[2][8];
    float h[64];
#pragma unroll
    for (int n = 0; n < 64; n++) h[n] = 0.f;
    float Dh = Dp[hh];
    size_t base = (size_t)s * L;

    for (int l = 0; l < L; ++l) {
        int buf = l & 1;
        const float* row = xbc + (base + l) * CONVD;
        if (tid < 128) {
            float val = row[DIN + tid];
            if (tid < 64) sB[buf][tid] = val; else sC[buf][tid - 64] = val;
        } else if (tid < 136) {
            sdt[buf][tid - 128] = dt[(base + l) * HEADS + (tid - 128)];
        } else if (tid < 144) {
            sdA[buf][tid - 136] = dA[(base + l) * HEADS + (tid - 136)];
        }
        float xv = row[tid];
        __syncthreads();
        float a   = sdA[buf][hh];
        float xdt = xv * sdt[buf][hh];
        float acc0 = 0.f, acc1 = 0.f, acc2 = 0.f, acc3 = 0.f;
#pragma unroll
        for (int n4 = 0; n4 < 16; ++n4) {
            float4 b4 = *(const float4*)&sB[buf][n4 * 4];
            float4 c4 = *(const float4*)&sC[buf][n4 * 4];
            int n = n4 * 4;
            h[n+0] = fmaf(a, h[n+0], xdt * b4.x); acc0 = fmaf(h[n+0], c4.x, acc0);
            h[n+1] = fmaf(a, h[n+1], xdt * b4.y); acc1 = fmaf(h[n+1], c4.y, acc1);
            h[n+2] = fmaf(a, h[n+2], xdt * b4.z); acc2 = fmaf(h[n+2], c4.z, acc2);
            h[n+3] = fmaf(a, h[n+3], xdt * b4.w); acc3 = fmaf(h[n+3], c4.w, acc3);
        }
        y[(base + l) * DIN + tid] = ((acc0 + acc1) + (acc2 + acc3)) + Dh * xv;
    }
}

// ---- gate (y * silu(z)) + rmsnorm-512 -> bf16 hi/lo : one warp / token ----
__global__ __launch_bounds__(256) void gate_k(const float* __restrict__ y,
                                              const float* __restrict__ zx,
                                              const float* __restrict__ gn,
                                              __nv_bfloat16* __restrict__ oh,
                                              __nv_bfloat16* __restrict__ ol)
{
    int warp = (blockIdx.x * blockDim.x + threadIdx.x) >> 5;
    int lane = threadIdx.x & 31;
    const float* yrow = y  + (size_t)warp * DIN;
    const float* zrow = zx + (size_t)warp * PROJ;
    float v[16]; float ss = 0.f;
#pragma unroll
    for (int i = 0; i < 16; i++) {
        int c = lane + i*32;
        float z  = zrow[c];
        float gv = yrow[c] * (z / (1.f + __expf(-z)));
        v[i] = gv; ss += gv * gv;
    }
#pragma unroll
    for (int o = 16; o > 0; o >>= 1) ss += __shfl_xor_sync(0xffffffffu, ss, o);
    float rs = rsqrtf(ss * (1.f/512.f) + 1e-6f);
    __nv_bfloat16* hrow = oh + (size_t)warp * DIN;
    __nv_bfloat16* lrow = ol + (size_t)warp * DIN;
#pragma unroll
    for (int i = 0; i < 16; i++) {
        int c = lane + i*32;
        float f = v[i] * rs * gn[c];
        __nv_bfloat16 h = __float2bfloat16(f);
        hrow[c] = h;
        lrow[c] = __float2bfloat16(f - __bfloat162float(h));
    }
}

// ---------------- transpose (2,64,512,H) -> (2,512,64,H) ----------------
__global__ __launch_bounds__(256) void transpose_k(const float* __restrict__ in,
                                                   float* __restrict__ out)
{
    size_t id = (size_t)blockIdx.x * 256 + threadIdx.x;
    int h4   = (int)(id & 63);
    int band = (int)((id >> 6) & 63);
    int t    = (int)((id >> 12) & 511);
    int b    = (int)(id >> 21);
    const float4* ip = (const float4*)in;
    ((float4*)out)[id] = ip[((((size_t)(b * 64 + band)) * 512 + t) << 6) + h4];
}

// ---------------- host-side orchestration ----------------
static void run_mamba(const float* io_in, float* io_out, int S, int L,
                      const float* norm,
                      const __nv_bfloat16* WinTh, const __nv_bfloat16* WinTl,
                      const float* cw, const float* cb, const float* dtb,
                      const float* Alog, const float* Dp, const float* gn,
                      const __nv_bfloat16* WoutTh, const __nv_bfloat16* WoutTl,
                      __nv_bfloat16* xh, __nv_bfloat16* xl,
                      float* zx, float* xbc, float* dtp, float* dAp, float* yb)
{
    rms256_k<<<TOK / 8, 256>>>(io_in, norm, xh, xl);
    {
        dim3 grid(NPAD / 128, TOK / 128);
        mma_gemm_k<<<grid, 256, GEMM_SMEM>>>(PROJ, HDIM, xh, xl, WinTh, WinTl, nullptr, zx);
    }
    dtda_k<<<(TOK * HEADS) / 256, 256>>>(zx, dtb, Alog, dtp, dAp);
    {
        int nch = L / 64;
        dim3 grid(S * nch, CONVD / 128);
        conv_k<<<grid, 128>>>(zx, cw, cb, xbc, L, nch);
    }
    scan_k<<<S, 512>>>(xbc, dtp, dAp, Dp, yb, L);
    gate_k<<<TOK / 8, 256>>>(yb, zx, gn, xh, xl);
    {
        dim3 grid(HDIM / 128, TOK / 128);
        mma_gemm_k<<<grid, 256, GEMM_SMEM>>>(HDIM, DIN, xh, xl, WoutTh, WoutTl, io_in, io_out);
    }
}

extern "C" void kernel_launch(void* const* d_in, const int* in_sizes, int n_in,
                              void* d_out, int out_size)
{
    const float* x = (const float*)d_in[0];
    const float* prm[2][9];
    for (int pth = 0; pth < 2; ++pth)
        for (int j = 0; j < 9; ++j)
            prm[pth][j] = (const float*)d_in[1 + pth * 9 + j];
    // order per path: norm, Win, cw, cb, dtb, Alog, D, gn, Wout

    cudaFuncSetAttribute(mma_gemm_k, cudaFuncAttributeMaxDynamicSharedMemorySize, GEMM_SMEM);

    float *bufA, *bufB, *zx, *xbc, *dtp, *dAp, *yb;
    __nv_bfloat16 *xh, *xl, *WinTh, *WinTl, *WoutTh, *WoutTl;
    cudaGetSymbolAddress((void**)&bufA, g_bufA);
    cudaGetSymbolAddress((void**)&bufB, g_bufB);
    cudaGetSymbolAddress((void**)&zx,  g_zx);
    cudaGetSymbolAddress((void**)&xbc, g_xbc);
    cudaGetSymbolAddress((void**)&dtp, g_dt);
    cudaGetSymbolAddress((void**)&dAp, g_dA);
    cudaGetSymbolAddress((void**)&yb,  g_y);
    cudaGetSymbolAddress((void**)&xh,  g_xh);
    cudaGetSymbolAddress((void**)&xl,  g_xl);
    cudaGetSymbolAddress((void**)&WinTh,  g_WinTh);
    cudaGetSymbolAddress((void**)&WinTl,  g_WinTl);
    cudaGetSymbolAddress((void**)&WoutTh, g_WoutTh);
    cudaGetSymbolAddress((void**)&WoutTl, g_WoutTl);

    // pre-transpose + bf16-split all weights
    for (int pth = 0; pth < 2; ++pth) {
        for (int i = 0; i < NL; ++i) {
            int idx = pth * NL + i;
            {
                int tot = NPAD * HDIM;
                wtrans_k<<<(tot + 255) / 256, 256>>>(
                    prm[pth][1] + (size_t)i * HDIM * PROJ,
                    WinTh + (size_t)idx * NPAD * HDIM,
                    WinTl + (size_t)idx * NPAD * HDIM,
                    HDIM, PROJ, NPAD);
            }
            {
                int tot = HDIM * DIN;
                wtrans_k<<<(tot + 255) / 256, 256>>>(
                    prm[pth][8] + (size_t)i * DIN * HDIM,
                    WoutTh + (size_t)idx * HDIM * DIN,
                    WoutTl + (size_t)idx * HDIM * DIN,
                    DIN, HDIM, HDIM);
            }
        }
    }

    cudaMemcpyAsync(bufA, x, XELEMS * sizeof(float), cudaMemcpyDeviceToDevice);

    float* cur = bufA;
    float* alt = bufB;
    const size_t nF4 = XELEMS / 4;

    for (int i = 0; i < NL; ++i) {
        // time path: 128 contiguous sequences of 512 tokens
        run_mamba(cur, cur, 128, 512,
                  prm[0][0] + (size_t)i * HDIM,
                  WinTh + (size_t)(0 * NL + i) * NPAD * HDIM,
                  WinTl + (size_t)(0 * NL + i) * NPAD * HDIM,
                  prm[0][2] + (size_t)i * 4 * CONVD,
                  prm[0][3] + (size_t)i * CONVD,
                  prm[0][4] + (size_t)i * HEADS,
                  prm[0][5] + (size_t)i * HEADS,
                  prm[0][6] + (size_t)i * HEADS,
                  prm[0][7] + (size_t)i * DIN,
                  WoutTh + (size_t)(0 * NL + i) * HDIM * DIN,
                  WoutTl + (size_t)(0 * NL + i) * HDIM * DIN,
                  xh, xl, zx, xbc, dtp, dAp, yb);

        transpose_k<<<(unsigned)(nF4 / 256), 256>>>(cur, alt);
        { float* tmp = cur; cur = alt; alt = tmp; }

        // band path: 1024 contiguous sequences of 64 tokens
        run_mamba(cur, cur, 1024, 64,
                  prm[1][0] + (size_t)i * HDIM,
                  WinTh + (size_t)(1 * NL + i) * NPAD * HDIM,
                  WinTl + (size_t)(1 * NL + i) * NPAD * HDIM,
                  prm[1][2] + (size_t)i * 4 * CONVD,
                  prm[1][3] + (size_t)i * CONVD,
                  prm[1][4] + (size_t)i * HEADS,
                  prm[1][5] + (size_t)i * HEADS,
                  prm[1][6] + (size_t)i * HEADS,
                  prm[1][7] + (size_t)i * DIN,
                  WoutTh + (size_t)(1 * NL + i) * HDIM * DIN,
                  WoutTl + (size_t)(1 * NL + i) * HDIM * DIN,
                  xh, xl, zx, xbc, dtp, dAp, yb);
    }

    cudaMemcpyAsync(d_out, cur, XELEMS * sizeof(float), cudaMemcpyDeviceToDevice);
}